// round 15
// baseline (speedup 1.0000x reference)
#include <cuda_runtime.h>
#include <cuda_fp16.h>
#include <cstdint>

#define BSZ 16
#define SDIM 1024
#define EDIM 1024
#define HDIM 2048
#define MSALL (BSZ * SDIM)

// ---------------- scratch (device globals; no allocations) ----------------
__device__ __half g_plh[(size_t)MSALL * EDIM];    // pl (half)
__device__ __half g_samh[(size_t)MSALL * EDIM];   // sam (half), later x (half)
__device__ __half g_qh[(size_t)MSALL * EDIM];     // q (half), later attn (half)
__device__ __half g_kh[(size_t)MSALL * EDIM];     // k (half), later ff (half)
__device__ __half g_vTh[(size_t)MSALL * EDIM];    // v^T per batch (half)
__device__ __half g_wh[(size_t)BSZ * SDIM * SDIM];// softmax weights exp(s) (half)
__device__ __half g_hh[(size_t)MSALL * HDIM];     // FFN hidden (half)
__device__ __half g_WqTh[EDIM * EDIM];
__device__ __half g_WkTh[EDIM * EDIM];
__device__ __half g_WvTh[EDIM * EDIM];
__device__ __half g_W1Th[EDIM * HDIM];
__device__ __half g_W2Th[EDIM * HDIM];
__device__ float g_part[BSZ * 64];
__device__ float g_binv[BSZ];
__device__ unsigned g_scnt[BSZ];                  // per-batch completion counters (self-wrapping)

// ---------------- fp16 warp-MMA GEMM (m16n8k16, ldmatrix, multistage) -----
// C[M,N] = alpha * A[M,K] @ B[N,K]^T. A,B half, K-major. C fp32 or half.
// CTA 128x128, BK=64, 3 stages, 128 threads, 4 warps (2x2) of 64x64.
#define BM 128
#define BN 128
#define BKH 64                                  // halves per k-iter
#define NSTAGE 3
#define HPAD 72                                 // halves per row (64 + 8 pad)
#define TILE_BYTES (BM * HPAD * 2)              // 18432
#define STAGE_BYTES (2 * TILE_BYTES)            // 36864
#define GEMM_SMEM (NSTAGE * STAGE_BYTES)        // 110592

__device__ __forceinline__ void cp_async16(uint32_t dst, const void* src) {
    size_t ga = __cvta_generic_to_global(src);
    asm volatile("cp.async.cg.shared.global [%0], [%1], 16;"
                 :: "r"(dst), "l"(ga) : "memory");
}

__device__ __forceinline__ void mma_f16(float* c, const uint32_t* a, const uint32_t* b) {
    asm volatile(
        "mma.sync.aligned.m16n8k16.row.col.f32.f16.f16.f32 "
        "{%0,%1,%2,%3}, {%4,%5,%6,%7}, {%8,%9}, {%0,%1,%2,%3};"
        : "+f"(c[0]), "+f"(c[1]), "+f"(c[2]), "+f"(c[3])
        : "r"(a[0]), "r"(a[1]), "r"(a[2]), "r"(a[3]), "r"(b[0]), "r"(b[1]));
}

#define LDSM_X4(r0, r1, r2, r3, addr) \
    asm volatile("ldmatrix.sync.aligned.m8n8.x4.shared.b16 {%0,%1,%2,%3}, [%4];" \
                 : "=r"(r0), "=r"(r1), "=r"(r2), "=r"(r3) : "r"(addr))

__device__ __forceinline__ uint32_t s2u(const void* p) {
    uint32_t a;
    asm("{ .reg .u64 t; cvta.to.shared.u64 t, %1; cvt.u32.u64 %0, t; }"
        : "=r"(a) : "l"(p));
    return a;
}

// load one 128x64-half tile (rows at stride HPAD) via cp.async, 128 threads
__device__ __forceinline__ void load_tile_h(const __half* base, int ldk, int r0,
                                            int kt, uint32_t st, int tid) {
#pragma unroll
    for (int i = 0; i < 8; i++) {
        int slot = tid + (i << 7);
        int row = slot >> 3;       // 0..127
        int ch = slot & 7;         // 16B chunk within 128B row data
        cp_async16(st + row * (HPAD * 2) + ch * 16,
                   base + (size_t)(r0 + row) * ldk + kt + ch * 8);
    }
}

// wait: steady-state allows NSTAGE-2 = 1 outstanding group
__device__ __forceinline__ void wait_groups(int rem) {
    if (rem >= 1)
        asm volatile("cp.async.wait_group 1;" ::: "memory");
    else
        asm volatile("cp.async.wait_group 0;" ::: "memory");
}

// ---- shared mainloop body: computes 128x128 fp32 acc for A,B K-major ----
struct FragAcc { float acc[4][8][4]; };

__device__ __forceinline__ void gemm_mainloop(
    const __half* A, const __half* B, int K,
    int m0, int n0, uint32_t sb, int tid, FragAcc& fa,
    uint32_t aoff, uint32_t boff)
{
    const int nk = K / BKH;
#pragma unroll
    for (int j = 0; j < NSTAGE - 1; j++) {
        uint32_t st = sb + j * STAGE_BYTES;
        load_tile_h(A, K, m0, j * BKH, st, tid);
        load_tile_h(B, K, n0, j * BKH, st + TILE_BYTES, tid);
        asm volatile("cp.async.commit_group;" ::: "memory");
    }

    for (int i = 0; i < nk; i++) {
        const int s = i % NSTAGE;
        wait_groups(nk - 1 - i);
        __syncthreads();

        int jn = i + NSTAGE - 1;
        if (jn < nk) {
            uint32_t st = sb + (jn % NSTAGE) * STAGE_BYTES;
            load_tile_h(A, K, m0, jn * BKH, st, tid);
            load_tile_h(B, K, n0, jn * BKH, st + TILE_BYTES, tid);
            asm volatile("cp.async.commit_group;" ::: "memory");
        }

        const uint32_t ab = sb + s * STAGE_BYTES + aoff;
        const uint32_t bb = sb + s * STAGE_BYTES + TILE_BYTES + boff;

#pragma unroll
        for (int ks = 0; ks < 4; ks++) {    // four k16 steps per BK=64
            uint32_t af[4][4], bf[8][2];
#pragma unroll
            for (int mf = 0; mf < 4; mf++)
                LDSM_X4(af[mf][0], af[mf][1], af[mf][2], af[mf][3],
                        ab + mf * (16 * HPAD * 2) + ks * 32);
#pragma unroll
            for (int np = 0; np < 4; np++)
                LDSM_X4(bf[2 * np][0], bf[2 * np][1],
                        bf[2 * np + 1][0], bf[2 * np + 1][1],
                        bb + np * (16 * HPAD * 2) + ks * 32);
#pragma unroll
            for (int mf = 0; mf < 4; mf++)
#pragma unroll
                for (int nf = 0; nf < 8; nf++)
                    mma_f16(fa.acc[mf][nf], af[mf], bf[nf]);
        }
    }
}

// ---------------- generic GEMM kernel ----------------
// EXPMODE: epilogue stores exp(alpha*acc) as half, accumulates per-batch sum,
// and the last CTA of each batch finalizes binv = 1/sum (fixed-order).
template <bool OUTH, bool EXPMODE>
__global__ __launch_bounds__(128, 2)
void gemm_h(const __half* __restrict__ A, const __half* __restrict__ B,
            void* __restrict__ Cv, int N, int K,
            long long sA, long long sB, long long sC,
            float alpha, const float* __restrict__ alphaPtr,
            float* __restrict__ part, float* __restrict__ binv,
            unsigned* __restrict__ scnt)
{
    extern __shared__ char smem[];
    const uint32_t sb = s2u(smem);
    const int tid = threadIdx.x;
    const int bz = blockIdx.z;
    A += (long long)bz * sA;
    B += (long long)bz * sB;
    const int m0 = blockIdx.y * BM;
    const int n0 = blockIdx.x * BN;

    const int warp = tid >> 5, lane = tid & 31;
    const int wm = (warp & 1) * 64;
    const int wn = (warp >> 1) * 64;
    const int lg = lane >> 2;
    const int lt = lane & 3;
    const uint32_t aoff = (wm + (lane & 15)) * (HPAD * 2) + (lane & 16);
    const uint32_t boff = (wn + (lane & 7) + ((lane & 16) >> 1)) * (HPAD * 2)
                          + ((lane & 8) << 1);

    FragAcc fa;
#pragma unroll
    for (int i = 0; i < 4; i++)
#pragma unroll
        for (int j = 0; j < 8; j++)
#pragma unroll
            for (int c = 0; c < 4; c++) fa.acc[i][j][c] = 0.f;

    gemm_mainloop(A, B, K, m0, n0, sb, tid, fa, aoff, boff);

    const float aeff = alpha * (alphaPtr ? alphaPtr[bz] : 1.f);
    float lsum = 0.f;
#pragma unroll
    for (int mf = 0; mf < 4; mf++) {
        int r0 = m0 + wm + mf * 16 + lg;
#pragma unroll
        for (int nf = 0; nf < 8; nf++) {
            int cc = n0 + wn + nf * 8 + 2 * lt;
            float v00 = fa.acc[mf][nf][0] * aeff;
            float v01 = fa.acc[mf][nf][1] * aeff;
            float v10 = fa.acc[mf][nf][2] * aeff;
            float v11 = fa.acc[mf][nf][3] * aeff;
            if (EXPMODE) {
                v00 = __expf(v00);
                v01 = __expf(v01);
                v10 = __expf(v10);
                v11 = __expf(v11);
            }
            if (OUTH) {
                __half* C = (__half*)Cv + (long long)bz * sC;
                __half2 h0 = __floats2half2_rn(v00, v01);
                __half2 h1 = __floats2half2_rn(v10, v11);
                *(__half2*)&C[(long long)r0 * N + cc] = h0;
                *(__half2*)&C[(long long)(r0 + 8) * N + cc] = h1;
                if (EXPMODE) {
                    float2 f0 = __half22float2(h0), f1 = __half22float2(h1);
                    lsum += (f0.x + f0.y) + (f1.x + f1.y);
                }
            } else {
                float* C = (float*)Cv + (long long)bz * sC;
                float2 a0; a0.x = v00; a0.y = v01;
                float2 a1; a1.x = v10; a1.y = v11;
                *(float2*)&C[(long long)r0 * N + cc] = a0;
                *(float2*)&C[(long long)(r0 + 8) * N + cc] = a1;
            }
        }
    }

    if (EXPMODE) {
        __shared__ float red[4];
#pragma unroll
        for (int o = 16; o > 0; o >>= 1)
            lsum += __shfl_xor_sync(0xffffffffu, lsum, o);
        if (lane == 0) red[warp] = lsum;
        __syncthreads();
        if (tid == 0) {
            float bs = (red[0] + red[1]) + (red[2] + red[3]);
            part[bz * 64 + blockIdx.y * 8 + blockIdx.x] = bs;
            __threadfence();
            unsigned done = atomicInc(&scnt[bz], 63u);  // wraps 63 -> 0 (self-reset)
            if (done == 63u) {
                float tot = 0.f;
#pragma unroll 1
                for (int i = 0; i < 64; i++) tot += __ldcg(&part[bz * 64 + i]);
                binv[bz] = 1.f / tot;
            }
        }
    }
}

// ---------------- fused q/k/vT kernel (one launch, z selects task) -------
__global__ __launch_bounds__(128, 2)
void qkv_kernel()
{
    extern __shared__ char smem[];
    const uint32_t sb = s2u(smem);
    const int tid = threadIdx.x;
    const int z = blockIdx.z;

    const __half* A;
    const __half* B;
    __half* C;
    int m0;
    const int n0 = blockIdx.x * BN;
    const long long sSE = (long long)SDIM * EDIM;

    if (z == 0) {          // q = pl @ WqT^T
        A = g_plh;  B = g_WqTh; C = g_qh;  m0 = blockIdx.y * BM;
    } else if (z == 1) {   // k = sam @ WkT^T
        A = g_samh; B = g_WkTh; C = g_kh;  m0 = blockIdx.y * BM;
    } else {               // vT_b = WvT @ sam_b^T
        int batch = blockIdx.y >> 3;
        m0 = (blockIdx.y & 7) * BM;
        A = g_WvTh; B = g_samh + (long long)batch * sSE;
        C = g_vTh + (long long)batch * sSE;
    }
    const int N = 1024, K = 1024;

    const int warp = tid >> 5, lane = tid & 31;
    const int wm = (warp & 1) * 64;
    const int wn = (warp >> 1) * 64;
    const int lg = lane >> 2;
    const int lt = lane & 3;
    const uint32_t aoff = (wm + (lane & 15)) * (HPAD * 2) + (lane & 16);
    const uint32_t boff = (wn + (lane & 7) + ((lane & 16) >> 1)) * (HPAD * 2)
                          + ((lane & 8) << 1);

    FragAcc fa;
#pragma unroll
    for (int i = 0; i < 4; i++)
#pragma unroll
        for (int j = 0; j < 8; j++)
#pragma unroll
            for (int c = 0; c < 4; c++) fa.acc[i][j][c] = 0.f;

    gemm_mainloop(A, B, K, m0, n0, sb, tid, fa, aoff, boff);

#pragma unroll
    for (int mf = 0; mf < 4; mf++) {
        int r0 = m0 + wm + mf * 16 + lg;
#pragma unroll
        for (int nf = 0; nf < 8; nf++) {
            int cc = n0 + wn + nf * 8 + 2 * lt;
            *(__half2*)&C[(long long)r0 * N + cc] =
                __floats2half2_rn(fa.acc[mf][nf][0], fa.acc[mf][nf][1]);
            *(__half2*)&C[(long long)(r0 + 8) * N + cc] =
                __floats2half2_rn(fa.acc[mf][nf][2], fa.acc[mf][nf][3]);
        }
    }
}

// ---------------- fp32 -> fp16 copy (both inputs, one launch) ------------
__global__ __launch_bounds__(256)
void tohalf2_kernel(const float* __restrict__ s0, __half2* __restrict__ d0,
                    const float* __restrict__ s1, __half2* __restrict__ d1,
                    int n4)
{
    int i = blockIdx.x * 256 + threadIdx.x;
    const float* s = (i < n4) ? s0 : s1;
    __half2* d = (i < n4) ? d0 : d1;
    int j = (i < n4) ? i : i - n4;
    float4 v = ((const float4*)s)[j];
    d[2 * j] = __floats2half2_rn(v.x, v.y);
    d[2 * j + 1] = __floats2half2_rn(v.z, v.w);
}

// ------ ALL weight transposes (Wq,Wk,Wv,W1,W2) in ONE flattened launch ----
__global__ void transpose_all_kernel(const float* __restrict__ Wq,
                                     const float* __restrict__ Wk,
                                     const float* __restrict__ Wv,
                                     const float* __restrict__ W1,
                                     const float* __restrict__ W2)
{
    __shared__ float tile[32][33];
    const int t = blockIdx.x;
    const float* src;
    __half* dst;
    int rows, cols, tx, ty;
    if (t < 3072) {
        int w = t >> 10;
        int lt2 = t & 1023;
        src = (w == 0) ? Wq : (w == 1) ? Wk : Wv;
        dst = (w == 0) ? g_WqTh : (w == 1) ? g_WkTh : g_WvTh;
        rows = EDIM; cols = EDIM;
        tx = lt2 & 31; ty = lt2 >> 5;
    } else if (t < 5120) {
        int lt2 = t - 3072;
        src = W1; dst = g_W1Th;
        rows = EDIM; cols = HDIM;
        tx = lt2 & 63; ty = lt2 >> 6;
    } else {
        int lt2 = t - 5120;
        src = W2; dst = g_W2Th;
        rows = HDIM; cols = EDIM;
        tx = lt2 & 31; ty = lt2 >> 5;
    }
    const int c0 = tx * 32, r0 = ty * 32;
    const int x = threadIdx.x, y = threadIdx.y;
#pragma unroll
    for (int i = 0; i < 32; i += 8)
        tile[y + i][x] = src[(long long)(r0 + y + i) * cols + c0 + x];
    __syncthreads();
#pragma unroll
    for (int i = 0; i < 32; i += 8)
        dst[(long long)(c0 + y + i) * rows + r0 + x] = __float2half_rn(tile[x][y + i]);
}

// ---- fused residual-add + LayerNorm, BOTH operands half ------------------
__global__ __launch_bounds__(256)
void add_ln_hh_kernel(const __half2* __restrict__ a, const __half2* __restrict__ res,
                      const float* __restrict__ gam, const float* __restrict__ bet,
                      float* __restrict__ out, __half2* __restrict__ out_h)
{
    const int row = blockIdx.x;
    const int t = threadIdx.x;
    const size_t base = (size_t)row * (EDIM / 2) + 2 * t;
    const float2 fa0 = __half22float2(a[base]);
    const float2 fa1 = __half22float2(a[base + 1]);
    const float2 fr0 = __half22float2(res[base]);
    const float2 fr1 = __half22float2(res[base + 1]);
    float x0 = fa0.x + fr0.x, x1 = fa0.y + fr0.y;
    float x2 = fa1.x + fr1.x, x3 = fa1.y + fr1.y;

    __shared__ float red[8];
    float s = (x0 + x1) + (x2 + x3);
#pragma unroll
    for (int o = 16; o > 0; o >>= 1) s += __shfl_xor_sync(0xffffffffu, s, o);
    if ((t & 31) == 0) red[t >> 5] = s;
    __syncthreads();
    float tot = red[0];
#pragma unroll
    for (int i = 1; i < 8; i++) tot += red[i];
    const float mean = tot * (1.f / EDIM);
    __syncthreads();

    const float d0 = x0 - mean, d1 = x1 - mean, d2 = x2 - mean, d3 = x3 - mean;
    float v = (d0 * d0 + d1 * d1) + (d2 * d2 + d3 * d3);
#pragma unroll
    for (int o = 16; o > 0; o >>= 1) v += __shfl_xor_sync(0xffffffffu, v, o);
    if ((t & 31) == 0) red[t >> 5] = v;
    __syncthreads();
    float vtot = red[0];
#pragma unroll
    for (int i = 1; i < 8; i++) vtot += red[i];
    const float rstd = rsqrtf(vtot * (1.f / EDIM) + 1e-5f);

    const float4 vg = ((const float4*)gam)[t];
    const float4 vb = ((const float4*)bet)[t];
    float4 o4;
    o4.x = d0 * rstd * vg.x + vb.x;
    o4.y = d1 * rstd * vg.y + vb.y;
    o4.z = d2 * rstd * vg.z + vb.z;
    o4.w = d3 * rstd * vg.w + vb.w;
    if (out)
        ((float4*)(out + (size_t)row * EDIM))[t] = o4;
    if (out_h) {
        out_h[base] = __floats2half2_rn(o4.x, o4.y);
        out_h[base + 1] = __floats2half2_rn(o4.z, o4.w);
    }
}

// ---------------- launch ----------------
extern "C" void kernel_launch(void* const* d_in, const int* in_sizes, int n_in,
                              void* d_out, int out_size)
{
    const float* pl   = (const float*)d_in[0];
    const float* sam  = (const float*)d_in[1];
    const float* Wq   = (const float*)d_in[2];
    const float* Wk   = (const float*)d_in[3];
    const float* Wv   = (const float*)d_in[4];
    const float* ln1g = (const float*)d_in[5];
    const float* ln1b = (const float*)d_in[6];
    const float* W1   = (const float*)d_in[7];
    const float* W2   = (const float*)d_in[8];
    const float* ln2g = (const float*)d_in[9];
    const float* ln2b = (const float*)d_in[10];
    float* out = (float*)d_out;

    __half *plh, *samh, *wh, *vTh, *hh;
    __half *qh, *kh;
    float *part, *binv;
    unsigned* scnt;
    cudaGetSymbolAddress((void**)&plh, g_plh);
    cudaGetSymbolAddress((void**)&samh, g_samh);
    cudaGetSymbolAddress((void**)&qh, g_qh);
    cudaGetSymbolAddress((void**)&kh, g_kh);
    cudaGetSymbolAddress((void**)&vTh, g_vTh);
    cudaGetSymbolAddress((void**)&wh, g_wh);
    cudaGetSymbolAddress((void**)&hh, g_hh);
    cudaGetSymbolAddress((void**)&part, g_part);
    cudaGetSymbolAddress((void**)&binv, g_binv);
    cudaGetSymbolAddress((void**)&scnt, g_scnt);

    __half *W1Th, *W2Th;
    cudaGetSymbolAddress((void**)&W1Th, g_W1Th);
    cudaGetSymbolAddress((void**)&W2Th, g_W2Th);

    cudaFuncSetAttribute((const void*)gemm_h<true, false>,
                         cudaFuncAttributeMaxDynamicSharedMemorySize, GEMM_SMEM);
    cudaFuncSetAttribute((const void*)gemm_h<true, true>,
                         cudaFuncAttributeMaxDynamicSharedMemorySize, GEMM_SMEM);
    cudaFuncSetAttribute((const void*)qkv_kernel,
                         cudaFuncAttributeMaxDynamicSharedMemorySize, GEMM_SMEM);

    const long long sSE = (long long)SDIM * EDIM;
    const long long sSS = (long long)SDIM * SDIM;

    // inputs -> half (single launch)
    {
        int n4 = MSALL * EDIM / 4;
        tohalf2_kernel<<<(2 * n4 + 255) / 256, 256>>>(
            pl, (__half2*)plh, sam, (__half2*)samh, n4);
    }

    // ALL weight transposes in one launch
    transpose_all_kernel<<<7168, dim3(32, 8)>>>(Wq, Wk, Wv, W1, W2);

    // q, k, vT in ONE launch (z: 0=q, 1=k, 2=vT batches via y)
    qkv_kernel<<<dim3(8, 128, 3), 128, GEMM_SMEM>>>();

    // weights wh = exp(scores) (half) + per-batch sum -> binv, fused
    gemm_h<true, true><<<dim3(8, 8, BSZ), 128, GEMM_SMEM>>>(
        qh, kh, wh, SDIM, EDIM, sSE, sSE, sSS, 0.03125f, nullptr,
        part, binv, scnt);

    // attn = (wh @ vT^T) * binv -> qh (HALF, reuses dead q buffer)
    gemm_h<true, false><<<dim3(8, 8, BSZ), 128, GEMM_SMEM>>>(
        wh, vTh, qh, EDIM, SDIM, sSS, sSE, sSE, 1.f, binv,
        nullptr, nullptr, nullptr);

    // x = LN(attn(half) + pl(half)): half only -> samh (reused)
    add_ln_hh_kernel<<<MSALL, 256>>>((const __half2*)qh, (const __half2*)plh,
                                     ln1g, ln1b, nullptr, (__half2*)samh);

    // h = x @ W1 (half out); ff = h @ W2 (HALF into kh, reuses dead k buffer)
    gemm_h<true, false><<<dim3(HDIM / BN, MSALL / BM, 1), 128, GEMM_SMEM>>>(
        samh, W1Th, hh, HDIM, EDIM, 0, 0, 0, 1.f, nullptr,
        nullptr, nullptr, nullptr);
    gemm_h<true, false><<<dim3(EDIM / BN, MSALL / BM, 1), 128, GEMM_SMEM>>>(
        hh, W2Th, kh, EDIM, HDIM, 0, 0, 0, 1.f, nullptr,
        nullptr, nullptr, nullptr);

    // out = LN(ff(half) + x(half)) -> fp32 output
    add_ln_hh_kernel<<<MSALL, 256>>>((const __half2*)kh, (const __half2*)samh,
                                     ln2g, ln2b, out, nullptr);
}

// round 16
// speedup vs baseline: 1.0427x; 1.0427x over previous
#include <cuda_runtime.h>
#include <cuda_fp16.h>
#include <cstdint>

#define BSZ 16
#define SDIM 1024
#define EDIM 1024
#define HDIM 2048
#define MSALL (BSZ * SDIM)

// ---------------- scratch (device globals; no allocations) ----------------
__device__ __half g_plh[(size_t)MSALL * EDIM];    // pl (half)
__device__ __half g_samh[(size_t)MSALL * EDIM];   // sam (half), later x (half)
__device__ __half g_qh[(size_t)MSALL * EDIM];     // q (half), later attn (half)
__device__ __half g_kh[(size_t)MSALL * EDIM];     // k (half), later ff (half)
__device__ __half g_vTh[(size_t)MSALL * EDIM];    // v^T per batch (half)
__device__ __half g_wh[(size_t)BSZ * SDIM * SDIM];// softmax weights exp(s) (half)
__device__ __half g_hh[(size_t)MSALL * HDIM];     // FFN hidden (half)
__device__ __half g_WqTh[EDIM * EDIM];
__device__ __half g_WkTh[EDIM * EDIM];
__device__ __half g_WvTh[EDIM * EDIM];
__device__ __half g_W1Th[EDIM * HDIM];
__device__ __half g_W2Th[EDIM * HDIM];
__device__ float g_part[BSZ * 64];
__device__ float g_binv[BSZ];
__device__ unsigned g_scnt[BSZ];                  // per-batch completion counters (self-wrapping)

// ---------------- fp16 warp-MMA GEMM (m16n8k16, ldmatrix, multistage) -----
// C[M,N] = alpha * A[M,K] @ B[N,K]^T. A,B half, K-major. C fp32 or half.
// CTA 128x128, BK=32, 5 stages, 128 threads, 4 warps (2x2) of 64x64.
#define BM 128
#define BN 128
#define BKH 32                                  // halves per k-iter
#define NSTAGE 5
#define HPAD 40                                 // halves per row (32 + 8 pad)
#define TILE_BYTES (BM * HPAD * 2)              // 10240
#define STAGE_BYTES (2 * TILE_BYTES)            // 20480
#define GEMM_SMEM (NSTAGE * STAGE_BYTES)        // 102400

__device__ __forceinline__ void cp_async16(uint32_t dst, const void* src) {
    size_t ga = __cvta_generic_to_global(src);
    asm volatile("cp.async.cg.shared.global [%0], [%1], 16;"
                 :: "r"(dst), "l"(ga) : "memory");
}

__device__ __forceinline__ void mma_f16(float* c, const uint32_t* a, const uint32_t* b) {
    asm volatile(
        "mma.sync.aligned.m16n8k16.row.col.f32.f16.f16.f32 "
        "{%0,%1,%2,%3}, {%4,%5,%6,%7}, {%8,%9}, {%0,%1,%2,%3};"
        : "+f"(c[0]), "+f"(c[1]), "+f"(c[2]), "+f"(c[3])
        : "r"(a[0]), "r"(a[1]), "r"(a[2]), "r"(a[3]), "r"(b[0]), "r"(b[1]));
}

#define LDSM_X4(r0, r1, r2, r3, addr) \
    asm volatile("ldmatrix.sync.aligned.m8n8.x4.shared.b16 {%0,%1,%2,%3}, [%4];" \
                 : "=r"(r0), "=r"(r1), "=r"(r2), "=r"(r3) : "r"(addr))

__device__ __forceinline__ uint32_t s2u(const void* p) {
    uint32_t a;
    asm("{ .reg .u64 t; cvta.to.shared.u64 t, %1; cvt.u32.u64 %0, t; }"
        : "=r"(a) : "l"(p));
    return a;
}

// load one 128x32-half tile (rows at stride HPAD) via cp.async, 128 threads
__device__ __forceinline__ void load_tile_h(const __half* base, int ldk, int r0,
                                            int kt, uint32_t st, int tid) {
#pragma unroll
    for (int i = 0; i < 4; i++) {
        int slot = tid + (i << 7);
        int row = slot >> 2;       // 0..127
        int ch = slot & 3;         // 16B chunk within 64B row
        cp_async16(st + row * (HPAD * 2) + ch * 16,
                   base + (size_t)(r0 + row) * ldk + kt + ch * 8);
    }
}

// generalized wait: allow at most `rem` (capped at NSTAGE-2) groups outstanding
__device__ __forceinline__ void wait_groups(int rem) {
    if (rem >= 3)
        asm volatile("cp.async.wait_group 3;" ::: "memory");
    else if (rem == 2)
        asm volatile("cp.async.wait_group 2;" ::: "memory");
    else if (rem == 1)
        asm volatile("cp.async.wait_group 1;" ::: "memory");
    else
        asm volatile("cp.async.wait_group 0;" ::: "memory");
}

// ---- shared mainloop body: computes 128x128 fp32 acc for A,B K-major ----
struct FragAcc { float acc[4][8][4]; };

__device__ __forceinline__ void gemm_mainloop(
    const __half* A, const __half* B, int K,
    int m0, int n0, uint32_t sb, int tid, FragAcc& fa,
    uint32_t aoff, uint32_t boff)
{
    const int nk = K / BKH;
#pragma unroll
    for (int j = 0; j < NSTAGE - 1; j++) {
        uint32_t st = sb + j * STAGE_BYTES;
        load_tile_h(A, K, m0, j * BKH, st, tid);
        load_tile_h(B, K, n0, j * BKH, st + TILE_BYTES, tid);
        asm volatile("cp.async.commit_group;" ::: "memory");
    }

    for (int i = 0; i < nk; i++) {
        const int s = i % NSTAGE;
        wait_groups(nk - 1 - i);
        __syncthreads();

        int jn = i + NSTAGE - 1;
        if (jn < nk) {
            uint32_t st = sb + (jn % NSTAGE) * STAGE_BYTES;
            load_tile_h(A, K, m0, jn * BKH, st, tid);
            load_tile_h(B, K, n0, jn * BKH, st + TILE_BYTES, tid);
            asm volatile("cp.async.commit_group;" ::: "memory");
        }

        const uint32_t ab = sb + s * STAGE_BYTES + aoff;
        const uint32_t bb = sb + s * STAGE_BYTES + TILE_BYTES + boff;

#pragma unroll
        for (int ks = 0; ks < 2; ks++) {
            uint32_t af[4][4], bf[8][2];
#pragma unroll
            for (int mf = 0; mf < 4; mf++)
                LDSM_X4(af[mf][0], af[mf][1], af[mf][2], af[mf][3],
                        ab + mf * (16 * HPAD * 2) + ks * 32);
#pragma unroll
            for (int np = 0; np < 4; np++)
                LDSM_X4(bf[2 * np][0], bf[2 * np][1],
                        bf[2 * np + 1][0], bf[2 * np + 1][1],
                        bb + np * (16 * HPAD * 2) + ks * 32);
#pragma unroll
            for (int mf = 0; mf < 4; mf++)
#pragma unroll
                for (int nf = 0; nf < 8; nf++)
                    mma_f16(fa.acc[mf][nf], af[mf], bf[nf]);
        }
    }
}

// ---------------- generic GEMM kernel ----------------
// EXPMODE: epilogue stores exp(alpha*acc) as half, accumulates per-batch sum,
// and the last CTA of each batch finalizes binv = 1/sum (fixed-order).
template <bool OUTH, bool EXPMODE>
__global__ __launch_bounds__(128, 2)
void gemm_h(const __half* __restrict__ A, const __half* __restrict__ B,
            void* __restrict__ Cv, int N, int K,
            long long sA, long long sB, long long sC,
            float alpha, const float* __restrict__ alphaPtr,
            float* __restrict__ part, float* __restrict__ binv,
            unsigned* __restrict__ scnt)
{
    extern __shared__ char smem[];
    const uint32_t sb = s2u(smem);
    const int tid = threadIdx.x;
    const int bz = blockIdx.z;
    A += (long long)bz * sA;
    B += (long long)bz * sB;
    const int m0 = blockIdx.y * BM;
    const int n0 = blockIdx.x * BN;

    const int warp = tid >> 5, lane = tid & 31;
    const int wm = (warp & 1) * 64;
    const int wn = (warp >> 1) * 64;
    const int lg = lane >> 2;
    const int lt = lane & 3;
    const uint32_t aoff = (wm + (lane & 15)) * (HPAD * 2) + (lane & 16);
    const uint32_t boff = (wn + (lane & 7) + ((lane & 16) >> 1)) * (HPAD * 2)
                          + ((lane & 8) << 1);

    FragAcc fa;
#pragma unroll
    for (int i = 0; i < 4; i++)
#pragma unroll
        for (int j = 0; j < 8; j++)
#pragma unroll
            for (int c = 0; c < 4; c++) fa.acc[i][j][c] = 0.f;

    gemm_mainloop(A, B, K, m0, n0, sb, tid, fa, aoff, boff);

    const float aeff = alpha * (alphaPtr ? alphaPtr[bz] : 1.f);
    float lsum = 0.f;
#pragma unroll
    for (int mf = 0; mf < 4; mf++) {
        int r0 = m0 + wm + mf * 16 + lg;
#pragma unroll
        for (int nf = 0; nf < 8; nf++) {
            int cc = n0 + wn + nf * 8 + 2 * lt;
            float v00 = fa.acc[mf][nf][0] * aeff;
            float v01 = fa.acc[mf][nf][1] * aeff;
            float v10 = fa.acc[mf][nf][2] * aeff;
            float v11 = fa.acc[mf][nf][3] * aeff;
            if (EXPMODE) {
                v00 = __expf(v00);
                v01 = __expf(v01);
                v10 = __expf(v10);
                v11 = __expf(v11);
            }
            if (OUTH) {
                __half* C = (__half*)Cv + (long long)bz * sC;
                __half2 h0 = __floats2half2_rn(v00, v01);
                __half2 h1 = __floats2half2_rn(v10, v11);
                *(__half2*)&C[(long long)r0 * N + cc] = h0;
                *(__half2*)&C[(long long)(r0 + 8) * N + cc] = h1;
                if (EXPMODE) {
                    float2 f0 = __half22float2(h0), f1 = __half22float2(h1);
                    lsum += (f0.x + f0.y) + (f1.x + f1.y);
                }
            } else {
                float* C = (float*)Cv + (long long)bz * sC;
                float2 a0; a0.x = v00; a0.y = v01;
                float2 a1; a1.x = v10; a1.y = v11;
                *(float2*)&C[(long long)r0 * N + cc] = a0;
                *(float2*)&C[(long long)(r0 + 8) * N + cc] = a1;
            }
        }
    }

    if (EXPMODE) {
        __shared__ float red[4];
#pragma unroll
        for (int o = 16; o > 0; o >>= 1)
            lsum += __shfl_xor_sync(0xffffffffu, lsum, o);
        if (lane == 0) red[warp] = lsum;
        __syncthreads();
        if (tid == 0) {
            float bs = (red[0] + red[1]) + (red[2] + red[3]);
            part[bz * 64 + blockIdx.y * 8 + blockIdx.x] = bs;
            __threadfence();
            unsigned done = atomicInc(&scnt[bz], 63u);  // wraps 63 -> 0 (self-reset)
            if (done == 63u) {
                float tot = 0.f;
#pragma unroll 1
                for (int i = 0; i < 64; i++) tot += __ldcg(&part[bz * 64 + i]);
                binv[bz] = 1.f / tot;
            }
        }
    }
}

// ---------------- fused q/k/vT kernel (one launch, z selects task) -------
__global__ __launch_bounds__(128, 2)
void qkv_kernel()
{
    extern __shared__ char smem[];
    const uint32_t sb = s2u(smem);
    const int tid = threadIdx.x;
    const int z = blockIdx.z;

    const __half* A;
    const __half* B;
    __half* C;
    int m0;
    const int n0 = blockIdx.x * BN;
    const long long sSE = (long long)SDIM * EDIM;

    if (z == 0) {          // q = pl @ WqT^T
        A = g_plh;  B = g_WqTh; C = g_qh;  m0 = blockIdx.y * BM;
    } else if (z == 1) {   // k = sam @ WkT^T
        A = g_samh; B = g_WkTh; C = g_kh;  m0 = blockIdx.y * BM;
    } else {               // vT_b = WvT @ sam_b^T
        int batch = blockIdx.y >> 3;
        m0 = (blockIdx.y & 7) * BM;
        A = g_WvTh; B = g_samh + (long long)batch * sSE;
        C = g_vTh + (long long)batch * sSE;
    }
    const int N = 1024, K = 1024;

    const int warp = tid >> 5, lane = tid & 31;
    const int wm = (warp & 1) * 64;
    const int wn = (warp >> 1) * 64;
    const int lg = lane >> 2;
    const int lt = lane & 3;
    const uint32_t aoff = (wm + (lane & 15)) * (HPAD * 2) + (lane & 16);
    const uint32_t boff = (wn + (lane & 7) + ((lane & 16) >> 1)) * (HPAD * 2)
                          + ((lane & 8) << 1);

    FragAcc fa;
#pragma unroll
    for (int i = 0; i < 4; i++)
#pragma unroll
        for (int j = 0; j < 8; j++)
#pragma unroll
            for (int c = 0; c < 4; c++) fa.acc[i][j][c] = 0.f;

    gemm_mainloop(A, B, K, m0, n0, sb, tid, fa, aoff, boff);

#pragma unroll
    for (int mf = 0; mf < 4; mf++) {
        int r0 = m0 + wm + mf * 16 + lg;
#pragma unroll
        for (int nf = 0; nf < 8; nf++) {
            int cc = n0 + wn + nf * 8 + 2 * lt;
            *(__half2*)&C[(long long)r0 * N + cc] =
                __floats2half2_rn(fa.acc[mf][nf][0], fa.acc[mf][nf][1]);
            *(__half2*)&C[(long long)(r0 + 8) * N + cc] =
                __floats2half2_rn(fa.acc[mf][nf][2], fa.acc[mf][nf][3]);
        }
    }
}

// ---------------- fp32 -> fp16 copy (both inputs, one launch) ------------
__global__ __launch_bounds__(256)
void tohalf2_kernel(const float* __restrict__ s0, __half2* __restrict__ d0,
                    const float* __restrict__ s1, __half2* __restrict__ d1,
                    int n4)
{
    int i = blockIdx.x * 256 + threadIdx.x;
    const float* s = (i < n4) ? s0 : s1;
    __half2* d = (i < n4) ? d0 : d1;
    int j = (i < n4) ? i : i - n4;
    float4 v = ((const float4*)s)[j];
    d[2 * j] = __floats2half2_rn(v.x, v.y);
    d[2 * j + 1] = __floats2half2_rn(v.z, v.w);
}

// ------ ALL weight transposes (Wq,Wk,Wv,W1,W2) in ONE flattened launch ----
// Tile map: [0,1024) Wq, [1024,2048) Wk, [2048,3072) Wv  (32x32 tiles of ExE)
//           [3072,5120) W1 (64x32 tiles: rows=E, cols=H)
//           [5120,7168) W2 (32x64 tiles: rows=H, cols=E)
__global__ void transpose_all_kernel(const float* __restrict__ Wq,
                                     const float* __restrict__ Wk,
                                     const float* __restrict__ Wv,
                                     const float* __restrict__ W1,
                                     const float* __restrict__ W2)
{
    __shared__ float tile[32][33];
    const int t = blockIdx.x;
    const float* src;
    __half* dst;
    int rows, cols, tx, ty;
    if (t < 3072) {
        int w = t >> 10;           // 0,1,2
        int lt2 = t & 1023;
        src = (w == 0) ? Wq : (w == 1) ? Wk : Wv;
        dst = (w == 0) ? g_WqTh : (w == 1) ? g_WkTh : g_WvTh;
        rows = EDIM; cols = EDIM;
        tx = lt2 & 31; ty = lt2 >> 5;
    } else if (t < 5120) {
        int lt2 = t - 3072;
        src = W1; dst = g_W1Th;
        rows = EDIM; cols = HDIM;
        tx = lt2 & 63; ty = lt2 >> 6;   // 64 x-tiles, 32 y-tiles
    } else {
        int lt2 = t - 5120;
        src = W2; dst = g_W2Th;
        rows = HDIM; cols = EDIM;
        tx = lt2 & 31; ty = lt2 >> 5;   // 32 x-tiles, 64 y-tiles
    }
    const int c0 = tx * 32, r0 = ty * 32;
    const int x = threadIdx.x, y = threadIdx.y;
#pragma unroll
    for (int i = 0; i < 32; i += 8)
        tile[y + i][x] = src[(long long)(r0 + y + i) * cols + c0 + x];
    __syncthreads();
#pragma unroll
    for (int i = 0; i < 32; i += 8)
        dst[(long long)(c0 + y + i) * rows + r0 + x] = __float2half_rn(tile[x][y + i]);
}

// ---- fused residual-add + LayerNorm, BOTH operands half ------------------
// out[row] = LN(half(a[row]) + half(res[row])) * gamma + beta
// Writes fp32 out (if non-null) and/or half out_h (if non-null).
__global__ __launch_bounds__(256)
void add_ln_hh_kernel(const __half2* __restrict__ a, const __half2* __restrict__ res,
                      const float* __restrict__ gam, const float* __restrict__ bet,
                      float* __restrict__ out, __half2* __restrict__ out_h)
{
    const int row = blockIdx.x;
    const int t = threadIdx.x;
    const size_t base = (size_t)row * (EDIM / 2) + 2 * t;
    const float2 fa0 = __half22float2(a[base]);
    const float2 fa1 = __half22float2(a[base + 1]);
    const float2 fr0 = __half22float2(res[base]);
    const float2 fr1 = __half22float2(res[base + 1]);
    float x0 = fa0.x + fr0.x, x1 = fa0.y + fr0.y;
    float x2 = fa1.x + fr1.x, x3 = fa1.y + fr1.y;

    __shared__ float red[8];
    float s = (x0 + x1) + (x2 + x3);
#pragma unroll
    for (int o = 16; o > 0; o >>= 1) s += __shfl_xor_sync(0xffffffffu, s, o);
    if ((t & 31) == 0) red[t >> 5] = s;
    __syncthreads();
    float tot = red[0];
#pragma unroll
    for (int i = 1; i < 8; i++) tot += red[i];
    const float mean = tot * (1.f / EDIM);
    __syncthreads();

    const float d0 = x0 - mean, d1 = x1 - mean, d2 = x2 - mean, d3 = x3 - mean;
    float v = (d0 * d0 + d1 * d1) + (d2 * d2 + d3 * d3);
#pragma unroll
    for (int o = 16; o > 0; o >>= 1) v += __shfl_xor_sync(0xffffffffu, v, o);
    if ((t & 31) == 0) red[t >> 5] = v;
    __syncthreads();
    float vtot = red[0];
#pragma unroll
    for (int i = 1; i < 8; i++) vtot += red[i];
    const float rstd = rsqrtf(vtot * (1.f / EDIM) + 1e-5f);

    const float4 vg = ((const float4*)gam)[t];
    const float4 vb = ((const float4*)bet)[t];
    float4 o4;
    o4.x = d0 * rstd * vg.x + vb.x;
    o4.y = d1 * rstd * vg.y + vb.y;
    o4.z = d2 * rstd * vg.z + vb.z;
    o4.w = d3 * rstd * vg.w + vb.w;
    if (out)
        ((float4*)(out + (size_t)row * EDIM))[t] = o4;
    if (out_h) {
        out_h[base] = __floats2half2_rn(o4.x, o4.y);
        out_h[base + 1] = __floats2half2_rn(o4.z, o4.w);
    }
}

// ---------------- launch ----------------
extern "C" void kernel_launch(void* const* d_in, const int* in_sizes, int n_in,
                              void* d_out, int out_size)
{
    const float* pl   = (const float*)d_in[0];
    const float* sam  = (const float*)d_in[1];
    const float* Wq   = (const float*)d_in[2];
    const float* Wk   = (const float*)d_in[3];
    const float* Wv   = (const float*)d_in[4];
    const float* ln1g = (const float*)d_in[5];
    const float* ln1b = (const float*)d_in[6];
    const float* W1   = (const float*)d_in[7];
    const float* W2   = (const float*)d_in[8];
    const float* ln2g = (const float*)d_in[9];
    const float* ln2b = (const float*)d_in[10];
    float* out = (float*)d_out;

    __half *plh, *samh, *wh, *vTh, *hh;
    __half *qh, *kh;
    float *part, *binv;
    unsigned* scnt;
    cudaGetSymbolAddress((void**)&plh, g_plh);
    cudaGetSymbolAddress((void**)&samh, g_samh);
    cudaGetSymbolAddress((void**)&qh, g_qh);
    cudaGetSymbolAddress((void**)&kh, g_kh);
    cudaGetSymbolAddress((void**)&vTh, g_vTh);
    cudaGetSymbolAddress((void**)&wh, g_wh);
    cudaGetSymbolAddress((void**)&hh, g_hh);
    cudaGetSymbolAddress((void**)&part, g_part);
    cudaGetSymbolAddress((void**)&binv, g_binv);
    cudaGetSymbolAddress((void**)&scnt, g_scnt);

    __half *W1Th, *W2Th;
    cudaGetSymbolAddress((void**)&W1Th, g_W1Th);
    cudaGetSymbolAddress((void**)&W2Th, g_W2Th);

    cudaFuncSetAttribute((const void*)gemm_h<true, false>,
                         cudaFuncAttributeMaxDynamicSharedMemorySize, GEMM_SMEM);
    cudaFuncSetAttribute((const void*)gemm_h<true, true>,
                         cudaFuncAttributeMaxDynamicSharedMemorySize, GEMM_SMEM);
    cudaFuncSetAttribute((const void*)qkv_kernel,
                         cudaFuncAttributeMaxDynamicSharedMemorySize, GEMM_SMEM);

    const long long sSE = (long long)SDIM * EDIM;
    const long long sSS = (long long)SDIM * SDIM;

    // inputs -> half (single launch)
    {
        int n4 = MSALL * EDIM / 4;
        tohalf2_kernel<<<(2 * n4 + 255) / 256, 256>>>(
            pl, (__half2*)plh, sam, (__half2*)samh, n4);
    }

    // ALL weight transposes in one launch
    transpose_all_kernel<<<7168, dim3(32, 8)>>>(Wq, Wk, Wv, W1, W2);

    // q, k, vT in ONE launch (z: 0=q, 1=k, 2=vT batches via y)
    qkv_kernel<<<dim3(8, 128, 3), 128, GEMM_SMEM>>>();

    // weights wh = exp(scores) (half) + per-batch sum -> binv, fused
    gemm_h<true, true><<<dim3(8, 8, BSZ), 128, GEMM_SMEM>>>(
        qh, kh, wh, SDIM, EDIM, sSE, sSE, sSS, 0.03125f, nullptr,
        part, binv, scnt);

    // attn = (wh @ vT^T) * binv -> qh (HALF, reuses dead q buffer)
    gemm_h<true, false><<<dim3(8, 8, BSZ), 128, GEMM_SMEM>>>(
        wh, vTh, qh, EDIM, SDIM, sSS, sSE, sSE, 1.f, binv,
        nullptr, nullptr, nullptr);

    // x = LN(attn(half) + pl(half)): half only -> samh (reused)
    add_ln_hh_kernel<<<MSALL, 256>>>((const __half2*)qh, (const __half2*)plh,
                                     ln1g, ln1b, nullptr, (__half2*)samh);

    // h = x @ W1 (half out); ff = h @ W2 (HALF into kh, reuses dead k buffer)
    gemm_h<true, false><<<dim3(HDIM / BN, MSALL / BM, 1), 128, GEMM_SMEM>>>(
        samh, W1Th, hh, HDIM, EDIM, 0, 0, 0, 1.f, nullptr,
        nullptr, nullptr, nullptr);
    gemm_h<true, false><<<dim3(EDIM / BN, MSALL / BM, 1), 128, GEMM_SMEM>>>(
        hh, W2Th, kh, EDIM, HDIM, 0, 0, 0, 1.f, nullptr,
        nullptr, nullptr, nullptr);

    // out = LN(ff(half) + x(half)) -> fp32 output
    add_ln_hh_kernel<<<MSALL, 256>>>((const __half2*)kh, (const __half2*)samh,
                                     ln2g, ln2b, out, nullptr);
}

// round 17
// speedup vs baseline: 1.0696x; 1.0258x over previous
#include <cuda_runtime.h>
#include <cuda_fp16.h>
#include <cstdint>

#define BSZ 16
#define SDIM 1024
#define EDIM 1024
#define HDIM 2048
#define MSALL (BSZ * SDIM)

// ---------------- scratch (device globals; no allocations) ----------------
__device__ __half g_plh[(size_t)MSALL * EDIM];    // pl (half)
__device__ __half g_samh[(size_t)MSALL * EDIM];   // sam (half), later x (half)
__device__ __half g_qh[(size_t)MSALL * EDIM];     // q (half), later attn (half)
__device__ __half g_kh[(size_t)MSALL * EDIM];     // k (half), later ff (half)
__device__ __half g_vTh[(size_t)MSALL * EDIM];    // v^T per batch (half)
__device__ __half g_wh[(size_t)BSZ * SDIM * SDIM];// softmax weights exp(s) (half)
__device__ __half g_hh[(size_t)MSALL * HDIM];     // FFN hidden (half)
__device__ __half g_WqTh[EDIM * EDIM];
__device__ __half g_WkTh[EDIM * EDIM];
__device__ __half g_WvTh[EDIM * EDIM];
__device__ __half g_W1Th[EDIM * HDIM];
__device__ __half g_W2Th[EDIM * HDIM];
__device__ float g_part[BSZ * 64];
__device__ float g_binv[BSZ];
__device__ unsigned g_scnt[BSZ];                  // per-batch completion counters (self-wrapping)

// ---------------- fp16 warp-MMA GEMM (m16n8k16, ldmatrix, multistage) -----
// C[M,N] = alpha * A[M,K] @ B[N,K]^T. A,B half, K-major. C fp32 or half.
// CTA 128x128, BK=32, 5 stages, 128 threads, 4 warps (2x2) of 64x64.
#define BM 128
#define BN 128
#define BKH 32                                  // halves per k-iter
#define NSTAGE 5
#define HPAD 40                                 // halves per row (32 + 8 pad)
#define TILE_BYTES (BM * HPAD * 2)              // 10240
#define STAGE_BYTES (2 * TILE_BYTES)            // 20480
#define GEMM_SMEM (NSTAGE * STAGE_BYTES)        // 102400

__device__ __forceinline__ void cp_async16(uint32_t dst, const void* src) {
    size_t ga = __cvta_generic_to_global(src);
    asm volatile("cp.async.cg.shared.global [%0], [%1], 16;"
                 :: "r"(dst), "l"(ga) : "memory");
}

__device__ __forceinline__ void mma_f16(float* c, const uint32_t* a, const uint32_t* b) {
    asm volatile(
        "mma.sync.aligned.m16n8k16.row.col.f32.f16.f16.f32 "
        "{%0,%1,%2,%3}, {%4,%5,%6,%7}, {%8,%9}, {%0,%1,%2,%3};"
        : "+f"(c[0]), "+f"(c[1]), "+f"(c[2]), "+f"(c[3])
        : "r"(a[0]), "r"(a[1]), "r"(a[2]), "r"(a[3]), "r"(b[0]), "r"(b[1]));
}

#define LDSM_X4(r0, r1, r2, r3, addr) \
    asm volatile("ldmatrix.sync.aligned.m8n8.x4.shared.b16 {%0,%1,%2,%3}, [%4];" \
                 : "=r"(r0), "=r"(r1), "=r"(r2), "=r"(r3) : "r"(addr))

__device__ __forceinline__ uint32_t s2u(const void* p) {
    uint32_t a;
    asm("{ .reg .u64 t; cvta.to.shared.u64 t, %1; cvt.u32.u64 %0, t; }"
        : "=r"(a) : "l"(p));
    return a;
}

// load one 128x32-half tile (rows at stride HPAD) via cp.async, 128 threads
__device__ __forceinline__ void load_tile_h(const __half* base, int ldk, int r0,
                                            int kt, uint32_t st, int tid) {
#pragma unroll
    for (int i = 0; i < 4; i++) {
        int slot = tid + (i << 7);
        int row = slot >> 2;       // 0..127
        int ch = slot & 3;         // 16B chunk within 64B row
        cp_async16(st + row * (HPAD * 2) + ch * 16,
                   base + (size_t)(r0 + row) * ldk + kt + ch * 8);
    }
}

// generalized wait: allow at most `rem` (capped at NSTAGE-2) groups outstanding
__device__ __forceinline__ void wait_groups(int rem) {
    if (rem >= 3)
        asm volatile("cp.async.wait_group 3;" ::: "memory");
    else if (rem == 2)
        asm volatile("cp.async.wait_group 2;" ::: "memory");
    else if (rem == 1)
        asm volatile("cp.async.wait_group 1;" ::: "memory");
    else
        asm volatile("cp.async.wait_group 0;" ::: "memory");
}

// ---- shared mainloop body: computes 128x128 fp32 acc for A,B K-major ----
struct FragAcc { float acc[4][8][4]; };

__device__ __forceinline__ void gemm_mainloop(
    const __half* A, const __half* B, int K,
    int m0, int n0, uint32_t sb, int tid, FragAcc& fa,
    uint32_t aoff, uint32_t boff)
{
    const int nk = K / BKH;
#pragma unroll
    for (int j = 0; j < NSTAGE - 1; j++) {
        uint32_t st = sb + j * STAGE_BYTES;
        load_tile_h(A, K, m0, j * BKH, st, tid);
        load_tile_h(B, K, n0, j * BKH, st + TILE_BYTES, tid);
        asm volatile("cp.async.commit_group;" ::: "memory");
    }

    for (int i = 0; i < nk; i++) {
        const int s = i % NSTAGE;
        wait_groups(nk - 1 - i);
        __syncthreads();

        int jn = i + NSTAGE - 1;
        if (jn < nk) {
            uint32_t st = sb + (jn % NSTAGE) * STAGE_BYTES;
            load_tile_h(A, K, m0, jn * BKH, st, tid);
            load_tile_h(B, K, n0, jn * BKH, st + TILE_BYTES, tid);
            asm volatile("cp.async.commit_group;" ::: "memory");
        }

        const uint32_t ab = sb + s * STAGE_BYTES + aoff;
        const uint32_t bb = sb + s * STAGE_BYTES + TILE_BYTES + boff;

#pragma unroll
        for (int ks = 0; ks < 2; ks++) {
            uint32_t af[4][4], bf[8][2];
#pragma unroll
            for (int mf = 0; mf < 4; mf++)
                LDSM_X4(af[mf][0], af[mf][1], af[mf][2], af[mf][3],
                        ab + mf * (16 * HPAD * 2) + ks * 32);
#pragma unroll
            for (int np = 0; np < 4; np++)
                LDSM_X4(bf[2 * np][0], bf[2 * np][1],
                        bf[2 * np + 1][0], bf[2 * np + 1][1],
                        bb + np * (16 * HPAD * 2) + ks * 32);
#pragma unroll
            for (int mf = 0; mf < 4; mf++)
#pragma unroll
                for (int nf = 0; nf < 8; nf++)
                    mma_f16(fa.acc[mf][nf], af[mf], bf[nf]);
        }
    }
}

// ---------------- generic GEMM kernel (half out) ----------------
__global__ __launch_bounds__(128, 2)
void gemm_h(const __half* __restrict__ A, const __half* __restrict__ B,
            __half* __restrict__ C, int N, int K,
            long long sA, long long sB, long long sC,
            const float* __restrict__ alphaPtr)
{
    extern __shared__ char smem[];
    const uint32_t sb = s2u(smem);
    const int tid = threadIdx.x;
    const int bz = blockIdx.z;
    A += (long long)bz * sA;
    B += (long long)bz * sB;
    C += (long long)bz * sC;
    const int m0 = blockIdx.y * BM;
    const int n0 = blockIdx.x * BN;

    const int warp = tid >> 5, lane = tid & 31;
    const int wm = (warp & 1) * 64;
    const int wn = (warp >> 1) * 64;
    const int lg = lane >> 2;
    const int lt = lane & 3;
    const uint32_t aoff = (wm + (lane & 15)) * (HPAD * 2) + (lane & 16);
    const uint32_t boff = (wn + (lane & 7) + ((lane & 16) >> 1)) * (HPAD * 2)
                          + ((lane & 8) << 1);

    FragAcc fa;
#pragma unroll
    for (int i = 0; i < 4; i++)
#pragma unroll
        for (int j = 0; j < 8; j++)
#pragma unroll
            for (int c = 0; c < 4; c++) fa.acc[i][j][c] = 0.f;

    gemm_mainloop(A, B, K, m0, n0, sb, tid, fa, aoff, boff);

    const float aeff = alphaPtr ? alphaPtr[bz] : 1.f;
#pragma unroll
    for (int mf = 0; mf < 4; mf++) {
        int r0 = m0 + wm + mf * 16 + lg;
#pragma unroll
        for (int nf = 0; nf < 8; nf++) {
            int cc = n0 + wn + nf * 8 + 2 * lt;
            *(__half2*)&C[(long long)r0 * N + cc] =
                __floats2half2_rn(fa.acc[mf][nf][0] * aeff, fa.acc[mf][nf][1] * aeff);
            *(__half2*)&C[(long long)(r0 + 8) * N + cc] =
                __floats2half2_rn(fa.acc[mf][nf][2] * aeff, fa.acc[mf][nf][3] * aeff);
        }
    }
}

// ---- combined scores(exp)+vT kernel: grid (8,8,32) ----
// z<16:  wh_b = exp(q_b @ k_b^T / 32), per-batch sum -> binv (last-CTA)
// z>=16: vT_b = WvT @ sam_b^T  (plain half store)
__global__ __launch_bounds__(128, 2)
void scores_vt_kernel(float* __restrict__ part, float* __restrict__ binv,
                      unsigned* __restrict__ scnt)
{
    extern __shared__ char smem[];
    const uint32_t sb = s2u(smem);
    const int tid = threadIdx.x;
    const int z = blockIdx.z;
    const long long sSE = (long long)SDIM * EDIM;
    const long long sSS = (long long)SDIM * SDIM;
    const bool doexp = (z < 16);

    const __half* A;
    const __half* B;
    __half* C;
    int bz;
    if (doexp) {
        bz = z;
        A = g_qh + (long long)bz * sSE;
        B = g_kh + (long long)bz * sSE;
        C = g_wh + (long long)bz * sSS;
    } else {
        bz = z - 16;
        A = g_WvTh;
        B = g_samh + (long long)bz * sSE;
        C = g_vTh + (long long)bz * sSE;
    }
    const int N = 1024, K = 1024;
    const int m0 = blockIdx.y * BM;
    const int n0 = blockIdx.x * BN;

    const int warp = tid >> 5, lane = tid & 31;
    const int wm = (warp & 1) * 64;
    const int wn = (warp >> 1) * 64;
    const int lg = lane >> 2;
    const int lt = lane & 3;
    const uint32_t aoff = (wm + (lane & 15)) * (HPAD * 2) + (lane & 16);
    const uint32_t boff = (wn + (lane & 7) + ((lane & 16) >> 1)) * (HPAD * 2)
                          + ((lane & 8) << 1);

    FragAcc fa;
#pragma unroll
    for (int i = 0; i < 4; i++)
#pragma unroll
        for (int j = 0; j < 8; j++)
#pragma unroll
            for (int c = 0; c < 4; c++) fa.acc[i][j][c] = 0.f;

    gemm_mainloop(A, B, K, m0, n0, sb, tid, fa, aoff, boff);

    if (doexp) {
        float lsum = 0.f;
#pragma unroll
        for (int mf = 0; mf < 4; mf++) {
            int r0 = m0 + wm + mf * 16 + lg;
#pragma unroll
            for (int nf = 0; nf < 8; nf++) {
                int cc = n0 + wn + nf * 8 + 2 * lt;
                __half2 h0 = __floats2half2_rn(__expf(fa.acc[mf][nf][0] * 0.03125f),
                                               __expf(fa.acc[mf][nf][1] * 0.03125f));
                __half2 h1 = __floats2half2_rn(__expf(fa.acc[mf][nf][2] * 0.03125f),
                                               __expf(fa.acc[mf][nf][3] * 0.03125f));
                *(__half2*)&C[(long long)r0 * N + cc] = h0;
                *(__half2*)&C[(long long)(r0 + 8) * N + cc] = h1;
                float2 f0 = __half22float2(h0), f1 = __half22float2(h1);
                lsum += (f0.x + f0.y) + (f1.x + f1.y);
            }
        }
        __shared__ float red[4];
#pragma unroll
        for (int o = 16; o > 0; o >>= 1)
            lsum += __shfl_xor_sync(0xffffffffu, lsum, o);
        if (lane == 0) red[warp] = lsum;
        __syncthreads();
        if (tid == 0) {
            float bs = (red[0] + red[1]) + (red[2] + red[3]);
            part[bz * 64 + blockIdx.y * 8 + blockIdx.x] = bs;
            __threadfence();
            unsigned done = atomicInc(&scnt[bz], 63u);  // wraps 63 -> 0 (self-reset)
            if (done == 63u) {
                float tot = 0.f;
#pragma unroll 1
                for (int i = 0; i < 64; i++) tot += __ldcg(&part[bz * 64 + i]);
                binv[bz] = 1.f / tot;
            }
        }
    } else {
#pragma unroll
        for (int mf = 0; mf < 4; mf++) {
            int r0 = m0 + wm + mf * 16 + lg;
#pragma unroll
            for (int nf = 0; nf < 8; nf++) {
                int cc = n0 + wn + nf * 8 + 2 * lt;
                *(__half2*)&C[(long long)r0 * N + cc] =
                    __floats2half2_rn(fa.acc[mf][nf][0], fa.acc[mf][nf][1]);
                *(__half2*)&C[(long long)(r0 + 8) * N + cc] =
                    __floats2half2_rn(fa.acc[mf][nf][2], fa.acc[mf][nf][3]);
            }
        }
    }
}

// ---------------- fused q/k kernel (one launch, z selects operand) -------
__global__ __launch_bounds__(128, 2)
void qk_kernel()
{
    extern __shared__ char smem[];
    const uint32_t sb = s2u(smem);
    const int tid = threadIdx.x;
    const int z = blockIdx.z;

    const __half* A = (z == 0) ? g_plh : g_samh;
    const __half* B = (z == 0) ? g_WqTh : g_WkTh;
    __half* C = (z == 0) ? g_qh : g_kh;
    const int m0 = blockIdx.y * BM;
    const int n0 = blockIdx.x * BN;
    const int N = 1024, K = 1024;

    const int warp = tid >> 5, lane = tid & 31;
    const int wm = (warp & 1) * 64;
    const int wn = (warp >> 1) * 64;
    const int lg = lane >> 2;
    const int lt = lane & 3;
    const uint32_t aoff = (wm + (lane & 15)) * (HPAD * 2) + (lane & 16);
    const uint32_t boff = (wn + (lane & 7) + ((lane & 16) >> 1)) * (HPAD * 2)
                          + ((lane & 8) << 1);

    FragAcc fa;
#pragma unroll
    for (int i = 0; i < 4; i++)
#pragma unroll
        for (int j = 0; j < 8; j++)
#pragma unroll
            for (int c = 0; c < 4; c++) fa.acc[i][j][c] = 0.f;

    gemm_mainloop(A, B, K, m0, n0, sb, tid, fa, aoff, boff);

#pragma unroll
    for (int mf = 0; mf < 4; mf++) {
        int r0 = m0 + wm + mf * 16 + lg;
#pragma unroll
        for (int nf = 0; nf < 8; nf++) {
            int cc = n0 + wn + nf * 8 + 2 * lt;
            *(__half2*)&C[(long long)r0 * N + cc] =
                __floats2half2_rn(fa.acc[mf][nf][0], fa.acc[mf][nf][1]);
            *(__half2*)&C[(long long)(r0 + 8) * N + cc] =
                __floats2half2_rn(fa.acc[mf][nf][2], fa.acc[mf][nf][3]);
        }
    }
}

// ---------------- fp32 -> fp16 copy (both inputs, one launch) ------------
__global__ __launch_bounds__(256)
void tohalf2_kernel(const float* __restrict__ s0, __half2* __restrict__ d0,
                    const float* __restrict__ s1, __half2* __restrict__ d1,
                    int n4)
{
    int i = blockIdx.x * 256 + threadIdx.x;
    const float* s = (i < n4) ? s0 : s1;
    __half2* d = (i < n4) ? d0 : d1;
    int j = (i < n4) ? i : i - n4;
    float4 v = ((const float4*)s)[j];
    d[2 * j] = __floats2half2_rn(v.x, v.y);
    d[2 * j + 1] = __floats2half2_rn(v.z, v.w);
}

// ------ ALL weight transposes (Wq,Wk,Wv,W1,W2) in ONE flattened launch ----
__global__ void transpose_all_kernel(const float* __restrict__ Wq,
                                     const float* __restrict__ Wk,
                                     const float* __restrict__ Wv,
                                     const float* __restrict__ W1,
                                     const float* __restrict__ W2)
{
    __shared__ float tile[32][33];
    const int t = blockIdx.x;
    const float* src;
    __half* dst;
    int rows, cols, tx, ty;
    if (t < 3072) {
        int w = t >> 10;
        int lt2 = t & 1023;
        src = (w == 0) ? Wq : (w == 1) ? Wk : Wv;
        dst = (w == 0) ? g_WqTh : (w == 1) ? g_WkTh : g_WvTh;
        rows = EDIM; cols = EDIM;
        tx = lt2 & 31; ty = lt2 >> 5;
    } else if (t < 5120) {
        int lt2 = t - 3072;
        src = W1; dst = g_W1Th;
        rows = EDIM; cols = HDIM;
        tx = lt2 & 63; ty = lt2 >> 6;
    } else {
        int lt2 = t - 5120;
        src = W2; dst = g_W2Th;
        rows = HDIM; cols = EDIM;
        tx = lt2 & 31; ty = lt2 >> 5;
    }
    const int c0 = tx * 32, r0 = ty * 32;
    const int x = threadIdx.x, y = threadIdx.y;
#pragma unroll
    for (int i = 0; i < 32; i += 8)
        tile[y + i][x] = src[(long long)(r0 + y + i) * cols + c0 + x];
    __syncthreads();
#pragma unroll
    for (int i = 0; i < 32; i += 8)
        dst[(long long)(c0 + y + i) * rows + r0 + x] = __float2half_rn(tile[x][y + i]);
}

// ---- fused residual-add + LayerNorm, BOTH operands half ------------------
__global__ __launch_bounds__(256)
void add_ln_hh_kernel(const __half2* __restrict__ a, const __half2* __restrict__ res,
                      const float* __restrict__ gam, const float* __restrict__ bet,
                      float* __restrict__ out, __half2* __restrict__ out_h)
{
    const int row = blockIdx.x;
    const int t = threadIdx.x;
    const size_t base = (size_t)row * (EDIM / 2) + 2 * t;
    const float2 fa0 = __half22float2(a[base]);
    const float2 fa1 = __half22float2(a[base + 1]);
    const float2 fr0 = __half22float2(res[base]);
    const float2 fr1 = __half22float2(res[base + 1]);
    float x0 = fa0.x + fr0.x, x1 = fa0.y + fr0.y;
    float x2 = fa1.x + fr1.x, x3 = fa1.y + fr1.y;

    __shared__ float red[8];
    float s = (x0 + x1) + (x2 + x3);
#pragma unroll
    for (int o = 16; o > 0; o >>= 1) s += __shfl_xor_sync(0xffffffffu, s, o);
    if ((t & 31) == 0) red[t >> 5] = s;
    __syncthreads();
    float tot = red[0];
#pragma unroll
    for (int i = 1; i < 8; i++) tot += red[i];
    const float mean = tot * (1.f / EDIM);
    __syncthreads();

    const float d0 = x0 - mean, d1 = x1 - mean, d2 = x2 - mean, d3 = x3 - mean;
    float v = (d0 * d0 + d1 * d1) + (d2 * d2 + d3 * d3);
#pragma unroll
    for (int o = 16; o > 0; o >>= 1) v += __shfl_xor_sync(0xffffffffu, v, o);
    if ((t & 31) == 0) red[t >> 5] = v;
    __syncthreads();
    float vtot = red[0];
#pragma unroll
    for (int i = 1; i < 8; i++) vtot += red[i];
    const float rstd = rsqrtf(vtot * (1.f / EDIM) + 1e-5f);

    const float4 vg = ((const float4*)gam)[t];
    const float4 vb = ((const float4*)bet)[t];
    float4 o4;
    o4.x = d0 * rstd * vg.x + vb.x;
    o4.y = d1 * rstd * vg.y + vb.y;
    o4.z = d2 * rstd * vg.z + vb.z;
    o4.w = d3 * rstd * vg.w + vb.w;
    if (out)
        ((float4*)(out + (size_t)row * EDIM))[t] = o4;
    if (out_h) {
        out_h[base] = __floats2half2_rn(o4.x, o4.y);
        out_h[base + 1] = __floats2half2_rn(o4.z, o4.w);
    }
}

// ---------------- launch ----------------
extern "C" void kernel_launch(void* const* d_in, const int* in_sizes, int n_in,
                              void* d_out, int out_size)
{
    const float* pl   = (const float*)d_in[0];
    const float* sam  = (const float*)d_in[1];
    const float* Wq   = (const float*)d_in[2];
    const float* Wk   = (const float*)d_in[3];
    const float* Wv   = (const float*)d_in[4];
    const float* ln1g = (const float*)d_in[5];
    const float* ln1b = (const float*)d_in[6];
    const float* W1   = (const float*)d_in[7];
    const float* W2   = (const float*)d_in[8];
    const float* ln2g = (const float*)d_in[9];
    const float* ln2b = (const float*)d_in[10];
    float* out = (float*)d_out;

    __half *plh, *samh, *hh, *qh, *kh;
    __half *W1Th, *W2Th;
    float *part, *binv;
    unsigned* scnt;
    cudaGetSymbolAddress((void**)&plh, g_plh);
    cudaGetSymbolAddress((void**)&samh, g_samh);
    cudaGetSymbolAddress((void**)&qh, g_qh);
    cudaGetSymbolAddress((void**)&kh, g_kh);
    cudaGetSymbolAddress((void**)&hh, g_hh);
    cudaGetSymbolAddress((void**)&W1Th, g_W1Th);
    cudaGetSymbolAddress((void**)&W2Th, g_W2Th);
    cudaGetSymbolAddress((void**)&part, g_part);
    cudaGetSymbolAddress((void**)&binv, g_binv);
    cudaGetSymbolAddress((void**)&scnt, g_scnt);

    __half *vTh, *wh;
    cudaGetSymbolAddress((void**)&vTh, g_vTh);
    cudaGetSymbolAddress((void**)&wh, g_wh);

    cudaFuncSetAttribute((const void*)gemm_h,
                         cudaFuncAttributeMaxDynamicSharedMemorySize, GEMM_SMEM);
    cudaFuncSetAttribute((const void*)scores_vt_kernel,
                         cudaFuncAttributeMaxDynamicSharedMemorySize, GEMM_SMEM);
    cudaFuncSetAttribute((const void*)qk_kernel,
                         cudaFuncAttributeMaxDynamicSharedMemorySize, GEMM_SMEM);

    const long long sSE = (long long)SDIM * EDIM;
    const long long sSS = (long long)SDIM * SDIM;

    // inputs -> half (single launch)
    {
        int n4 = MSALL * EDIM / 4;
        tohalf2_kernel<<<(2 * n4 + 255) / 256, 256>>>(
            pl, (__half2*)plh, sam, (__half2*)samh, n4);
    }

    // ALL weight transposes in one launch
    transpose_all_kernel<<<7168, dim3(32, 8)>>>(Wq, Wk, Wv, W1, W2);

    // q, k in ONE launch (z: 0=q, 1=k)
    qk_kernel<<<dim3(8, 128, 2), 128, GEMM_SMEM>>>();

    // combined: scores->exp(wh)+binv (z<16) and vT (z>=16), one 2048-CTA launch
    scores_vt_kernel<<<dim3(8, 8, 32), 128, GEMM_SMEM>>>(part, binv, scnt);

    // attn = (wh @ vT^T) * binv -> qh (HALF, reuses dead q buffer)
    gemm_h<<<dim3(8, 8, BSZ), 128, GEMM_SMEM>>>(
        wh, vTh, qh, EDIM, SDIM, sSS, sSE, sSE, binv);

    // x = LN(attn(half) + pl(half)): half only -> samh (reused)
    add_ln_hh_kernel<<<MSALL, 256>>>((const __half2*)qh, (const __half2*)plh,
                                     ln1g, ln1b, nullptr, (__half2*)samh);

    // h = x @ W1 (half out); ff = h @ W2 (HALF into kh, reuses dead k buffer)
    gemm_h<<<dim3(HDIM / BN, MSALL / BM, 1), 128, GEMM_SMEM>>>(
        samh, W1Th, hh, HDIM, EDIM, 0, 0, 0, nullptr);
    gemm_h<<<dim3(EDIM / BN, MSALL / BM, 1), 128, GEMM_SMEM>>>(
        hh, W2Th, kh, EDIM, HDIM, 0, 0, 0, nullptr);

    // out = LN(ff(half) + x(half)) -> fp32 output
    add_ln_hh_kernel<<<MSALL, 256>>>((const __half2*)kh, (const __half2*)samh,
                                     ln2g, ln2b, out, nullptr);
}